// round 7
// baseline (speedup 1.0000x reference)
#include <cuda_runtime.h>

#define HW (768*768)

// XLA algebraic-simplifier semantics: x / const -> x * (1/const)
#define C3  (1.0f / 3.0f)
#define C81 (1.0f / 81.0f)

// packed f32x2 add: two independent rn fp32 adds (bit-exact per lane)
__device__ __forceinline__ unsigned long long addx2(unsigned long long a, unsigned long long b) {
    unsigned long long r;
    asm("add.rn.f32x2 %0, %1, %2;" : "=l"(r) : "l"(a), "l"(b));
    return r;
}
// packed operand builders
__device__ __forceinline__ unsigned long long dup2(float w) {
    unsigned long long r; asm("mov.b64 %0, {%1, %1};" : "=l"(r) : "f"(w)); return r;
}
__device__ __forceinline__ unsigned long long lo0(float w) {   // (w, +0)
    unsigned long long r; asm("mov.b64 %0, {%1, %2};" : "=l"(r) : "f"(w), "f"(0.0f)); return r;
}
__device__ __forceinline__ unsigned long long hi0(float w) {   // (+0, w)
    unsigned long long r; asm("mov.b64 %0, {%1, %2};" : "=l"(r) : "f"(0.0f), "f"(w)); return r;
}

// column-only swizzle for P2 (consistent bijection; conflict-free per 8-lane phase)
__device__ __forceinline__ unsigned csw(int c) {
    return (unsigned)((c * 8) ^ (c & 16));
}

// dynamic smem layout (bytes); P2 pitch 76 float2 = 608 B (bit4-clear stride)
#define P2_OFF 0                        // 40 x 76 float2 (pxx,pyy)        : 24320
#define P1_OFF 24320                    // 40 x 76 float  (pxy)            : 12160
#define M_OFF  36480                    // 42 x 80 float  (channel mean)   : 13440
#define SMEM_BYTES 49920

// one product row -> this thread's accumulators. MODE 0: first row (only out
// row 0); 1: middle (both); 2: last (only out row 1). xy packed across the two
// output rows (lane0=row0, lane1=row1). Per-lane order = reduce_window flat
// row-major: rows ascending (caller), cols c=0..8 ascending (here).
template<int MODE>
__device__ __forceinline__ void row_update(
    const char* __restrict__ P2b, const float4* __restrict__ P1v,
    unsigned (&ap2)[6], int& ip1,
    unsigned long long (&a2)[2][4], unsigned long long (&axy2)[4])
{
    unsigned long long w2[12];
    #pragma unroll
    for (int k = 0; k < 6; k++) {
        ulonglong2 q = *(const ulonglong2*)(P2b + ap2[k]);
        w2[2 * k] = q.x; w2[2 * k + 1] = q.y;
        ap2[k] += 608;
    }
    float w1[12];
    float4 f0 = P1v[ip1], f1 = P1v[ip1 + 1], f2 = P1v[ip1 + 2];
    ip1 += 19;
    w1[0] = f0.x; w1[1] = f0.y; w1[2]  = f0.z; w1[3]  = f0.w;
    w1[4] = f1.x; w1[5] = f1.y; w1[6]  = f1.z; w1[7]  = f1.w;
    w1[8] = f2.x; w1[9] = f2.y; w1[10] = f2.z; w1[11] = f2.w;

    #pragma unroll
    for (int cc = 0; cc < 4; cc++) {
        #pragma unroll
        for (int c = 0; c < 9; c++) {
            if (MODE != 2) a2[0][cc] = addx2(a2[0][cc], w2[cc + c]);
            if (MODE != 0) a2[1][cc] = addx2(a2[1][cc], w2[cc + c]);
            unsigned long long wd = (MODE == 0) ? lo0(w1[cc + c])
                                  : (MODE == 2) ? hi0(w1[cc + c])
                                                : dup2(w1[cc + c]);
            axy2[cc] = addx2(axy2[cc], wd);
        }
    }
}

__global__ void __launch_bounds__(256, 4) k_fused(const float* __restrict__ x,
                                                  float* __restrict__ out) {
    extern __shared__ char smem[];
    char*  P2b = smem + P2_OFF;
    float* P1  = (float*)(smem + P1_OFF);
    float* M   = (float*)(smem + M_OFF);

    const int col0 = blockIdx.x * 64;
    const int row0 = blockIdx.y * 32;
    const int b    = blockIdx.z;
    const int t    = threadIdx.x;
    const float* xb = x + (size_t)b * 3 * HW;

    // ---- Phase A: M[42][80] = channel mean; M[0][0] <-> src (row0-5, col0-8).
    for (int s = t; s < 42 * 20; s += 256) {
        int mr = s / 20, k = s - mr * 20;
        int gr = row0 - 5 + mr;
        int gc = col0 - 8 + 4 * k;
        float4 v = make_float4(0.f, 0.f, 0.f, 0.f);
        if ((unsigned)gr < 768u && (unsigned)gc <= 764u) {
            size_t off = (size_t)gr * 768 + gc;
            float4 a  = *(const float4*)(xb + off);
            float4 c1 = *(const float4*)(xb + HW + off);
            float4 c2 = *(const float4*)(xb + 2 * HW + off);
            v.x = __fmul_rn(__fadd_rn(__fadd_rn(a.x, c1.x), c2.x), C3);
            v.y = __fmul_rn(__fadd_rn(__fadd_rn(a.y, c1.y), c2.y), C3);
            v.z = __fmul_rn(__fadd_rn(__fadd_rn(a.z, c1.z), c2.z), C3);
            v.w = __fmul_rn(__fadd_rn(__fadd_rn(a.w, c1.w), c2.w), C3);
        }
        *(float4*)&M[mr * 80 + 4 * k] = v;
    }
    __syncthreads();

    // ---- Phase B: Sobel (exact reference op order) + products into P2/P1.
    //      P(pr,pc) <-> src (row0-4+pr, col0-4+pc); OOB -> 0.
    for (int s = t; s < 40 * 72; s += 256) {
        int pr = s / 72, pc = s - pr * 72;
        int sr = row0 - 4 + pr, sc = col0 - 4 + pc;
        float pxx = 0.f, pyy = 0.f, pxy = 0.f;
        if ((unsigned)sr < 768u && (unsigned)sc < 768u) {
            int mr = pr + 1, mc = pc + 4;
            const float* r0p = &M[(mr - 1) * 80 + mc];
            const float* r1p = &M[ mr      * 80 + mc];
            const float* r2p = &M[(mr + 1) * 80 + mc];
            float m00 = r0p[-1], m01 = r0p[0], m02 = r0p[1];
            float m10 = r1p[-1],               m12 = r1p[1];
            float m20 = r2p[-1], m21 = r2p[0], m22 = r2p[1];

            float rlx_u = __fsub_rn(m02, m00);
            float rlx_c = __fsub_rn(m12, m10);
            float rlx_d = __fsub_rn(m22, m20);
            float tx3 = __fadd_rn(__fadd_rn(rlx_u, rlx_c), rlx_d);
            float sxv = __fadd_rn(rlx_c, __fmul_rn(__fmul_rn(tx3, C3), 3.f));

            float btx_l = __fsub_rn(m20, m00);
            float btx_c = __fsub_rn(m21, m01);
            float btx_r = __fsub_rn(m22, m02);
            float ty3 = __fadd_rn(__fadd_rn(btx_l, btx_c), btx_r);
            float syv = __fadd_rn(btx_c, __fmul_rn(__fmul_rn(ty3, C3), 3.f));

            pxx = __fmul_rn(sxv, sxv);
            pyy = __fmul_rn(syv, syv);
            pxy = __fmul_rn(sxv, syv);
        }
        *(float2*)(P2b + pr * 608 + csw(pc)) = make_float2(pxx, pyy);
        P1[pr * 76 + pc] = pxy;
    }
    __syncthreads();

    // ---- Phase C: 2 rows x 4 cols per thread; 10-row sweep, carried addresses.
    const int uj = t & 15, ui = t >> 4;
    const int oc   = uj * 4;
    const int orow = ui * 2;

    unsigned long long a2[2][4];
    unsigned long long axy2[4];
    #pragma unroll
    for (int cc = 0; cc < 4; cc++) { a2[0][cc] = 0ull; a2[1][cc] = 0ull; axy2[cc] = 0ull; }

    unsigned ap2[6];
    #pragma unroll
    for (int k = 0; k < 6; k++) ap2[k] = (unsigned)(orow * 608) + csw(oc + 2 * k);
    const float4* P1v = (const float4*)P1;
    int ip1 = orow * 19 + uj;      // (orow*76 + oc)/4

    row_update<0>(P2b, P1v, ap2, ip1, a2, axy2);
    row_update<1>(P2b, P1v, ap2, ip1, a2, axy2);
    row_update<1>(P2b, P1v, ap2, ip1, a2, axy2);
    row_update<1>(P2b, P1v, ap2, ip1, a2, axy2);
    row_update<1>(P2b, P1v, ap2, ip1, a2, axy2);
    row_update<1>(P2b, P1v, ap2, ip1, a2, axy2);
    row_update<1>(P2b, P1v, ap2, ip1, a2, axy2);
    row_update<1>(P2b, P1v, ap2, ip1, a2, axy2);
    row_update<1>(P2b, P1v, ap2, ip1, a2, axy2);
    row_update<2>(P2b, P1v, ap2, ip1, a2, axy2);

    // ---- eigen-direction math (strict rn, identical to R3-R6) + store
    float* ob = out + (size_t)b * 3 * HW;
    #pragma unroll
    for (int oi = 0; oi < 2; oi++) {
        float ex4[4], ey4[4];
        #pragma unroll
        for (int cc = 0; cc < 4; cc++) {
            unsigned long long v = a2[oi][cc];
            float xx = __fmul_rn(__uint_as_float((unsigned)v), C81);
            float yy = __fmul_rn(__uint_as_float((unsigned)(v >> 32)), C81);
            unsigned long long vq = axy2[cc];
            float xyr = (oi == 0) ? __uint_as_float((unsigned)vq)
                                  : __uint_as_float((unsigned)(vq >> 32));
            float xy = __fmul_rn(xyr, C81);
            float bq = -__fadd_rn(xx, yy);
            float cq = __fsub_rn(__fmul_rn(xx, yy), __fmul_rn(xy, xy));
            float disc = __fsub_rn(__fmul_rn(bq, bq), __fmul_rn(4.f, cq));
            disc = fmaxf(disc, 0.f);
            float deta = __fsqrt_rn(disc);
            float l1 = __fmul_rn(__fadd_rn(-bq, deta), 0.5f);
            float yd = __fsub_rn(xx, l1);
            float s2 = __fadd_rn(__fadd_rn(__fmul_rn(xy, xy), __fmul_rn(yd, yd)), 1e-8f);
            float l  = __fadd_rn(__fsqrt_rn(s2), 1e-8f);
            ex4[cc] = __fdiv_rn(xy, l);
            ey4[cc] = __fdiv_rn(yd, l);
        }
        size_t o = (size_t)(row0 + orow + oi) * 768 + (col0 + oc);
        *(float4*)&ob[o]          = make_float4(ex4[0], ex4[1], ex4[2], ex4[3]);
        *(float4*)&ob[o + HW]     = make_float4(ey4[0], ey4[1], ey4[2], ey4[3]);
        *(float4*)&ob[o + 2*HW]   = make_float4(ex4[0], ex4[1], ex4[2], ex4[3]);
    }
}

extern "C" void kernel_launch(void* const* d_in, const int* in_sizes, int n_in,
                              void* d_out, int out_size) {
    const float* x = (const float*)d_in[0];
    float* out = (float*)d_out;

    cudaFuncSetAttribute(k_fused, cudaFuncAttributeMaxDynamicSharedMemorySize, SMEM_BYTES);
    dim3 grid(768 / 64, 768 / 32, 32);   // (12, 24, 32)
    k_fused<<<grid, 256, SMEM_BYTES>>>(x, out);
}